// round 13
// baseline (speedup 1.0000x reference)
#include <cuda_runtime.h>
#include <stdint.h>

#define NMAX   100000
#define EMAX   1600000
#define DIN    128
#define DOUT   32
#define CAP    64        // per-node source bucket capacity (deg ~ Poisson(16))
#define BM     128
#define BK     32

// ---- scratch (no allocations allowed) ----
__device__ float g_h[NMAX * DOUT];        // RAW x@W (never rescaled)
__device__ float g_dinv[NMAX];            // (deg)^{-1/2}, deg = in-edges + 1
__device__ int   g_fill[NMAX + 2];        // [0..NMAX): in-degree; [NMAX]: ovf cnt; [NMAX+1]: block counter
__device__ int   g_srcs[NMAX * CAP];      // bucketed sources per dst
__device__ int   g_ovf[2 * EMAX];         // overflow (src,dst) pairs

// ---------------------------------------------------------------------------
// Bucket placement (R8 formulation — binder is L2-side atomic service).
// Dtype detection per block: int64 (LE, values < 2^31) => all odd 32-bit
// words zero; 256 random int32 samples all-zero has prob ~1e-1280.
// ---------------------------------------------------------------------------
__global__ void k_place(const void* __restrict__ ei, int E) {
    __shared__ int s_is64;
    if (threadIdx.x == 0) s_is64 = 1;
    __syncthreads();
    if (((const unsigned*)ei)[2 * threadIdx.x + 1] != 0u) s_is64 = 0;
    __syncthreads();
    int is64 = s_is64;

    int e = blockIdx.x * blockDim.x + threadIdx.x;
    if (e >= E) return;
    int src, dst;
    if (is64) {
        src = (int)((const long long*)ei)[e];
        dst = (int)((const long long*)ei)[(long long)E + e];
    } else {
        src = ((const int*)ei)[e];
        dst = ((const int*)ei)[E + e];
    }
    int pos = atomicAdd(&g_fill[dst], 1);
    if (pos < CAP) {
        g_srcs[dst * CAP + pos] = src;
    } else {
        int o = atomicAdd(&g_fill[NMAX], 1);
        if (o < EMAX) { g_ovf[2 * o] = src; g_ovf[2 * o + 1] = dst; }
    }
}

// ---------------------------------------------------------------------------
// Tiny epilogue of the place branch: dinv = rsqrt(1 + deg). 0.8 MB total,
// hidden under the concurrently-running gemm branch.
// ---------------------------------------------------------------------------
__global__ void k_dinv(int n) {
    int i = blockIdx.x * 256 + threadIdx.x;
    if (i < n) g_dinv[i] = rsqrtf(1.0f + (float)g_fill[i]);
}

// ---------------------------------------------------------------------------
// GEMM mainloop (no g_fill dependency -> runs concurrently with k_place).
// 128x32 tile, BK=32, 4x4 micro-tile. Writes RAW acc to g_h.
// x is read exactly once -> __ldcs (streaming hint) keeps it from thrashing
// L2 slices that k_place's atomics are hammering concurrently.
// ---------------------------------------------------------------------------
__global__ void k_gemm(const float* __restrict__ x, const float* __restrict__ W,
                       int n) {
    __shared__ float xs[BM][BK + 1];   // 16.5 KB
    __shared__ float ws[BK][DOUT];     // 4 KB
    int t = threadIdx.x;
    int row0 = blockIdx.x * BM;
    int tx = t & 7, ty = t >> 3;

    float4 acc[4];
#pragma unroll
    for (int i = 0; i < 4; i++) acc[i] = make_float4(0.f, 0.f, 0.f, 0.f);

    for (int kc = 0; kc < DIN; kc += BK) {
#pragma unroll
        for (int it = 0; it < 4; it++) {
            int i = t + it * 256;
            int r = i >> 3, k4 = i & 7;
            int gr = row0 + r;
            float4 v = make_float4(0.f, 0.f, 0.f, 0.f);
            if (gr < n)
                v = __ldcs((const float4*)&x[(size_t)gr * DIN + kc + k4 * 4]);
            xs[r][k4 * 4 + 0] = v.x;
            xs[r][k4 * 4 + 1] = v.y;
            xs[r][k4 * 4 + 2] = v.z;
            xs[r][k4 * 4 + 3] = v.w;
        }
        ((float4*)ws)[t] = ((const float4*)(W + kc * DOUT))[t];
        __syncthreads();

#pragma unroll
        for (int k = 0; k < BK; k++) {
            float a0 = xs[ty * 4 + 0][k];
            float a1 = xs[ty * 4 + 1][k];
            float a2 = xs[ty * 4 + 2][k];
            float a3 = xs[ty * 4 + 3][k];
            float4 bw = *(float4*)&ws[k][tx * 4];
            acc[0].x = fmaf(a0, bw.x, acc[0].x); acc[0].y = fmaf(a0, bw.y, acc[0].y);
            acc[0].z = fmaf(a0, bw.z, acc[0].z); acc[0].w = fmaf(a0, bw.w, acc[0].w);
            acc[1].x = fmaf(a1, bw.x, acc[1].x); acc[1].y = fmaf(a1, bw.y, acc[1].y);
            acc[1].z = fmaf(a1, bw.z, acc[1].z); acc[1].w = fmaf(a1, bw.w, acc[1].w);
            acc[2].x = fmaf(a2, bw.x, acc[2].x); acc[2].y = fmaf(a2, bw.y, acc[2].y);
            acc[2].z = fmaf(a2, bw.z, acc[2].z); acc[2].w = fmaf(a2, bw.w, acc[2].w);
            acc[3].x = fmaf(a3, bw.x, acc[3].x); acc[3].y = fmaf(a3, bw.y, acc[3].y);
            acc[3].z = fmaf(a3, bw.z, acc[3].z); acc[3].w = fmaf(a3, bw.w, acc[3].w);
        }
        __syncthreads();
    }

#pragma unroll
    for (int i = 0; i < 4; i++) {
        int row = row0 + ty * 4 + i;
        if (row >= n) break;
        *(float4*)&g_h[row * DOUT + tx * 4] = acc[i];
    }
}

// ---------------------------------------------------------------------------
// Aggregation + full epilogue, out is WRITE-ONLY (no RMW):
//   out[d] = dd^2 * h_raw[d] + dd * sum_s(h_raw[s] * dinv[s]) + b
// Speculative front batch: srcs, cnt, dd, h_self row (all depend only on d);
// then per-edge h[s] AND dinv[s] gathered in parallel (same chain level).
// Overflow spill handled by the LAST block (threadfence + completion counter
// => cleanup's atomics ordered after every agg store).
// ---------------------------------------------------------------------------
__device__ __forceinline__ int clampidx(int s) {
    return ((unsigned)s < (unsigned)NMAX) ? s : 0;
}

__global__ void __launch_bounds__(128) k_agg(const float* __restrict__ b,
                                             float* __restrict__ out, int n) {
    __shared__ int s_last;
    int warp = threadIdx.x >> 5, lane = threadIdx.x & 31;
    int d = blockIdx.x * 4 + warp;
    int q  = lane >> 3;
    int c4 = lane & 7;

    if (d < n) {
        const int* sr = &g_srcs[d * CAP];

        // front batch (all independent; addresses depend only on d)
        int s0 = clampidx(sr[q]);
        int s1 = clampidx(sr[4 + q]);
        int s2 = clampidx(sr[8 + q]);
        int s3 = clampidx(sr[12 + q]);
        int cnt_raw = g_fill[d];
        float dd = g_dinv[d];
        float4 hself = *(const float4*)&g_h[d * DOUT + c4 * 4];
        float4 bb = *(const float4*)&b[c4 * 4];

        // parallel per-edge gathers: h row + dinv (same chain level)
        float dv0 = g_dinv[s0];
        float dv1 = g_dinv[s1];
        float dv2 = g_dinv[s2];
        float dv3 = g_dinv[s3];
        float4 h0 = *(const float4*)&g_h[s0 * DOUT + c4 * 4];
        float4 h1 = *(const float4*)&g_h[s1 * DOUT + c4 * 4];
        float4 h2 = *(const float4*)&g_h[s2 * DOUT + c4 * 4];
        float4 h3 = *(const float4*)&g_h[s3 * DOUT + c4 * 4];

        int cnt = cnt_raw > CAP ? CAP : cnt_raw;

        float4 a0 = make_float4(0.f, 0.f, 0.f, 0.f);
        float4 a1 = make_float4(0.f, 0.f, 0.f, 0.f);
        if (q < cnt) {
            a0.x = fmaf(h0.x, dv0, a0.x); a0.y = fmaf(h0.y, dv0, a0.y);
            a0.z = fmaf(h0.z, dv0, a0.z); a0.w = fmaf(h0.w, dv0, a0.w);
        }
        if (4 + q < cnt) {
            a1.x = fmaf(h1.x, dv1, a1.x); a1.y = fmaf(h1.y, dv1, a1.y);
            a1.z = fmaf(h1.z, dv1, a1.z); a1.w = fmaf(h1.w, dv1, a1.w);
        }
        if (8 + q < cnt) {
            a0.x = fmaf(h2.x, dv2, a0.x); a0.y = fmaf(h2.y, dv2, a0.y);
            a0.z = fmaf(h2.z, dv2, a0.z); a0.w = fmaf(h2.w, dv2, a0.w);
        }
        if (12 + q < cnt) {
            a1.x = fmaf(h3.x, dv3, a1.x); a1.y = fmaf(h3.y, dv3, a1.y);
            a1.z = fmaf(h3.z, dv3, a1.z); a1.w = fmaf(h3.w, dv3, a1.w);
        }

        for (int j = 16; j < cnt; j += 8) {
            int t0 = clampidx(sr[j + q]);
            int t1 = clampidx(sr[j + 4 + q]);
            float e0 = g_dinv[t0];
            float e1 = g_dinv[t1];
            float4 g0 = *(const float4*)&g_h[t0 * DOUT + c4 * 4];
            float4 g1 = *(const float4*)&g_h[t1 * DOUT + c4 * 4];
            if (j + q < cnt) {
                a0.x = fmaf(g0.x, e0, a0.x); a0.y = fmaf(g0.y, e0, a0.y);
                a0.z = fmaf(g0.z, e0, a0.z); a0.w = fmaf(g0.w, e0, a0.w);
            }
            if (j + 4 + q < cnt) {
                a1.x = fmaf(g1.x, e1, a1.x); a1.y = fmaf(g1.y, e1, a1.y);
                a1.z = fmaf(g1.z, e1, a1.z); a1.w = fmaf(g1.w, e1, a1.w);
            }
        }

        a0.x += a1.x; a0.y += a1.y; a0.z += a1.z; a0.w += a1.w;

        // reduce quarters (lane bits 3,4)
        a0.x += __shfl_xor_sync(0xffffffffu, a0.x, 8);
        a0.y += __shfl_xor_sync(0xffffffffu, a0.y, 8);
        a0.z += __shfl_xor_sync(0xffffffffu, a0.z, 8);
        a0.w += __shfl_xor_sync(0xffffffffu, a0.w, 8);
        a0.x += __shfl_xor_sync(0xffffffffu, a0.x, 16);
        a0.y += __shfl_xor_sync(0xffffffffu, a0.y, 16);
        a0.z += __shfl_xor_sync(0xffffffffu, a0.z, 16);
        a0.w += __shfl_xor_sync(0xffffffffu, a0.w, 16);

        if (lane < 8) {
            // out = ((hself*dd + sum) * dd) + b  =  dd^2*hself + dd*sum + b
            float4 o;
            o.x = fmaf(fmaf(hself.x, dd, a0.x), dd, bb.x);
            o.y = fmaf(fmaf(hself.y, dd, a0.y), dd, bb.y);
            o.z = fmaf(fmaf(hself.z, dd, a0.z), dd, bb.z);
            o.w = fmaf(fmaf(hself.w, dd, a0.w), dd, bb.w);
            *(float4*)&out[d * DOUT + c4 * 4] = o;
        }
    }

    // ---- last-block overflow cleanup (cold path, normally 0 spill) ----
    __threadfence();                 // each thread publishes its stores
    __syncthreads();
    if (threadIdx.x == 0) {
        int done = atomicAdd(&g_fill[NMAX + 1], 1);
        s_last = (done == (int)gridDim.x - 1) ? 1 : 0;
    }
    __syncthreads();
    if (s_last) {
        int cnt = g_fill[NMAX];
        if (cnt > EMAX) cnt = EMAX;
        for (int idx = threadIdx.x; idx < cnt * DOUT; idx += 128) {
            int o = idx >> 5, c = idx & 31;
            int src = g_ovf[2 * o], dst = g_ovf[2 * o + 1];
            atomicAdd(&out[dst * DOUT + c],
                      g_dinv[dst] * g_dinv[src] * g_h[src * DOUT + c]);
        }
    }
}

// ---------------------------------------------------------------------------
// Launch graph:
//   s0: memset(fill) -> k_place -> k_dinv ─┐
//   s2: k_gemm (independent)              ─┴─ join -> k_agg
// Stream/events created lazily on the FIRST (uncaptured) call only.
// ---------------------------------------------------------------------------
extern "C" void kernel_launch(void* const* d_in, const int* in_sizes, int n_in,
                              void* d_out, int out_size) {
    const float* x  = (const float*)d_in[0];
    const void*  ei = d_in[1];
    const float* W  = (const float*)d_in[2];
    const float* b  = (const float*)d_in[3];
    float* out = (float*)d_out;

    int n = in_sizes[0] / DIN;   // 100000
    int E = in_sizes[1] / 2;     // 1600000

    static cudaStream_t s2 = nullptr;
    static cudaEvent_t evFork = nullptr, evJoin = nullptr;
    if (!s2) {
        cudaStreamCreateWithFlags(&s2, cudaStreamNonBlocking);
        cudaEventCreateWithFlags(&evFork, cudaEventDisableTiming);
        cudaEventCreateWithFlags(&evJoin, cudaEventDisableTiming);
    }

    void* fill_ptr = nullptr;
    cudaGetSymbolAddress(&fill_ptr, g_fill);

    // fork: gemm branch on s2 (touches only x, W, g_h)
    cudaEventRecord(evFork, 0);
    cudaStreamWaitEvent(s2, evFork, 0);
    k_gemm<<<(n + BM - 1) / BM, 256, 0, s2>>>(x, W, n);
    cudaEventRecord(evJoin, s2);

    // place branch on stream 0
    cudaMemsetAsync(fill_ptr, 0, (NMAX + 2) * sizeof(int), 0);
    k_place<<<(E + 255) / 256, 256>>>(ei, E);
    k_dinv<<<(n + 255) / 256, 256>>>(n);

    // join, then aggregation (writes out directly; no k_scale)
    cudaStreamWaitEvent(0, evJoin, 0);
    k_agg<<<(n + 3) / 4, 128>>>(b, out, n);
}

// round 14
// speedup vs baseline: 1.2755x; 1.2755x over previous
#include <cuda_runtime.h>
#include <stdint.h>

typedef unsigned long long ull;

#define NMAX   100000
#define EMAX   1600000
#define DIN    128
#define DOUT   32
#define CAP    64        // per-node source bucket capacity (deg ~ Poisson(16))
#define BM     128
#define BK     32

// ---- scratch (no allocations allowed) ----
__device__ float g_h[NMAX * DOUT];        // raw x@W, scaled in k_scale
__device__ float g_dinv[NMAX];            // (deg)^{-1/2}, deg = in-edges + 1
__device__ int   g_fill[NMAX + 1];        // [0..NMAX): in-degree; [NMAX]: ovf count
__device__ int   g_srcs[NMAX * CAP];      // bucketed sources per dst
__device__ int   g_ovf[2 * EMAX];         // overflow (src,dst) pairs

__device__ __forceinline__ ull pack_dup(float a) {
    ull r;
    asm("mov.b64 %0, {%1, %1};" : "=l"(r) : "f"(a));
    return r;
}
__device__ __forceinline__ void fma2(ull& acc, ull a, ull b) {
    asm("fma.rn.f32x2 %0, %1, %2, %0;" : "+l"(acc) : "l"(a), "l"(b));
}
__device__ __forceinline__ float2 unpack2(ull v) {
    float lo, hi;
    asm("mov.b64 {%0, %1}, %2;" : "=f"(lo), "=f"(hi) : "l"(v));
    return make_float2(lo, hi);
}

// ---------------------------------------------------------------------------
// Bucket placement (R8 formulation — binder is L2-side atomic service).
// Dtype detection per block: int64 (LE, values < 2^31) => all odd 32-bit
// words zero; 256 random int32 samples all-zero has prob ~1e-1280.
// ---------------------------------------------------------------------------
__global__ void k_place(const void* __restrict__ ei, int E) {
    __shared__ int s_is64;
    if (threadIdx.x == 0) s_is64 = 1;
    __syncthreads();
    if (((const unsigned*)ei)[2 * threadIdx.x + 1] != 0u) s_is64 = 0;
    __syncthreads();
    int is64 = s_is64;

    int e = blockIdx.x * blockDim.x + threadIdx.x;
    if (e >= E) return;
    int src, dst;
    if (is64) {
        src = (int)((const long long*)ei)[e];
        dst = (int)((const long long*)ei)[(long long)E + e];
    } else {
        src = ((const int*)ei)[e];
        dst = ((const int*)ei)[E + e];
    }
    int pos = atomicAdd(&g_fill[dst], 1);
    if (pos < CAP) {
        g_srcs[dst * CAP + pos] = src;
    } else {
        int o = atomicAdd(&g_fill[NMAX], 1);
        if (o < EMAX) { g_ovf[2 * o] = src; g_ovf[2 * o + 1] = dst; }
    }
}

// ---------------------------------------------------------------------------
// GEMM mainloop (no g_fill dependency -> runs concurrently with k_place).
// R7 tiles/staging preserved exactly; inner product upgraded to FFMA2 paired
// across COLUMN pairs: acc2[i][j] = {col 2j, col 2j+1} of row i. Per k:
// 4 scalar x-LDS + 1 LDS.128 of w (reinterpreted as 2 packed ulls) +
// 4 mov.b64 {a,a} + 8 FFMA2 (was 16 FFMA). Same register footprint, same
// occupancy; per-element FMA chains are bit-identical to the scalar version.
// Writes RAW acc to g_h. x read once -> __ldcs streaming hint.
// ---------------------------------------------------------------------------
__global__ void k_gemm(const float* __restrict__ x, const float* __restrict__ W,
                       int n) {
    __shared__ float xs[BM][BK + 1];   // 16.5 KB
    __shared__ float ws[BK][DOUT];     // 4 KB
    int t = threadIdx.x;
    int row0 = blockIdx.x * BM;
    int tx = t & 7, ty = t >> 3;

    ull acc2[4][2];
#pragma unroll
    for (int i = 0; i < 4; i++) { acc2[i][0] = 0ull; acc2[i][1] = 0ull; }

    for (int kc = 0; kc < DIN; kc += BK) {
#pragma unroll
        for (int it = 0; it < 4; it++) {
            int i = t + it * 256;
            int r = i >> 3, k4 = i & 7;
            int gr = row0 + r;
            float4 v = make_float4(0.f, 0.f, 0.f, 0.f);
            if (gr < n)
                v = __ldcs((const float4*)&x[(size_t)gr * DIN + kc + k4 * 4]);
            xs[r][k4 * 4 + 0] = v.x;
            xs[r][k4 * 4 + 1] = v.y;
            xs[r][k4 * 4 + 2] = v.z;
            xs[r][k4 * 4 + 3] = v.w;
        }
        ((float4*)ws)[t] = ((const float4*)(W + kc * DOUT))[t];
        __syncthreads();

#pragma unroll
        for (int k = 0; k < BK; k++) {
            float a0 = xs[ty * 4 + 0][k];
            float a1 = xs[ty * 4 + 1][k];
            float a2 = xs[ty * 4 + 2][k];
            float a3 = xs[ty * 4 + 3][k];
            ulonglong2 w = *(const ulonglong2*)&ws[k][tx * 4];  // {c0,c1},{c2,c3}
            ull p0 = pack_dup(a0), p1 = pack_dup(a1);
            ull p2 = pack_dup(a2), p3 = pack_dup(a3);
            fma2(acc2[0][0], p0, w.x); fma2(acc2[0][1], p0, w.y);
            fma2(acc2[1][0], p1, w.x); fma2(acc2[1][1], p1, w.y);
            fma2(acc2[2][0], p2, w.x); fma2(acc2[2][1], p2, w.y);
            fma2(acc2[3][0], p3, w.x); fma2(acc2[3][1], p3, w.y);
        }
        __syncthreads();
    }

#pragma unroll
    for (int i = 0; i < 4; i++) {
        int row = row0 + ty * 4 + i;
        if (row >= n) break;
        float2 lo = unpack2(acc2[i][0]);
        float2 hi = unpack2(acc2[i][1]);
        float4 o = make_float4(lo.x, lo.y, hi.x, hi.y);
        *(float4*)&g_h[row * DOUT + tx * 4] = o;
    }
}

// ---------------------------------------------------------------------------
// Join epilogue: dinv = rsqrt(1+deg); g_h *= dinv; out = g_h*dinv + b.
// ---------------------------------------------------------------------------
__global__ void k_scale(const float* __restrict__ b, float* __restrict__ out, int n) {
    int tid = blockIdx.x * 256 + threadIdx.x;
    int row = tid >> 3, c4 = tid & 7;
    if (row >= n) return;
    float dinv = rsqrtf(1.0f + (float)g_fill[row]);
    if (c4 == 0) g_dinv[row] = dinv;
    float4 a = *(float4*)&g_h[row * DOUT + c4 * 4];
    float4 hs = make_float4(a.x * dinv, a.y * dinv, a.z * dinv, a.w * dinv);
    *(float4*)&g_h[row * DOUT + c4 * 4] = hs;
    float4 bb = *(const float4*)&b[c4 * 4];
    float4 o;
    o.x = fmaf(hs.x, dinv, bb.x);
    o.y = fmaf(hs.y, dinv, bb.y);
    o.z = fmaf(hs.z, dinv, bb.z);
    o.w = fmaf(hs.w, dinv, bb.w);
    *(float4*)&out[row * DOUT + c4 * 4] = o;
}

// ---------------------------------------------------------------------------
// Pull-side aggregation (speculative front batch) + overflow-cleanup blocks.
// (R11-proven: 27.6 us.)
// ---------------------------------------------------------------------------
__device__ __forceinline__ int clampidx(int s) {
    return ((unsigned)s < (unsigned)NMAX) ? s : 0;
}

__global__ void __launch_bounds__(128) k_agg(float* __restrict__ out, int n, int nb_agg) {
    if (blockIdx.x >= nb_agg) {
        int cnt = g_fill[NMAX];
        if (cnt > EMAX) cnt = EMAX;
        int tid = (blockIdx.x - nb_agg) * 128 + threadIdx.x;
        for (int o = tid; o < cnt; o += 16 * 128) {
            int src = g_ovf[2 * o], dst = g_ovf[2 * o + 1];
            float nrm = g_dinv[dst];
            for (int c = 0; c < DOUT; c++)
                atomicAdd(&out[dst * DOUT + c], g_h[src * DOUT + c] * nrm);
        }
        return;
    }

    int warp = threadIdx.x >> 5, lane = threadIdx.x & 31;
    int d = blockIdx.x * 4 + warp;
    if (d >= n) return;

    int q  = lane >> 3;
    int c4 = lane & 7;

    const int* sr = &g_srcs[d * CAP];

    // parallel front batch (addresses depend only on d)
    int s0 = clampidx(sr[q]);
    int s1 = clampidx(sr[4 + q]);
    int s2 = clampidx(sr[8 + q]);
    int s3 = clampidx(sr[12 + q]);
    int cnt_raw = g_fill[d];
    float dd = g_dinv[d];
    float4* op = (float4*)&out[d * DOUT + c4 * 4];
    float4 oval = *op;

    float4 h0 = *(const float4*)&g_h[s0 * DOUT + c4 * 4];
    float4 h1 = *(const float4*)&g_h[s1 * DOUT + c4 * 4];
    float4 h2 = *(const float4*)&g_h[s2 * DOUT + c4 * 4];
    float4 h3 = *(const float4*)&g_h[s3 * DOUT + c4 * 4];

    int cnt = cnt_raw > CAP ? CAP : cnt_raw;

    float4 a0 = make_float4(0.f, 0.f, 0.f, 0.f);
    float4 a1 = make_float4(0.f, 0.f, 0.f, 0.f);
    if (q      < cnt) { a0.x += h0.x; a0.y += h0.y; a0.z += h0.z; a0.w += h0.w; }
    if (4 + q  < cnt) { a1.x += h1.x; a1.y += h1.y; a1.z += h1.z; a1.w += h1.w; }
    if (8 + q  < cnt) { a0.x += h2.x; a0.y += h2.y; a0.z += h2.z; a0.w += h2.w; }
    if (12 + q < cnt) { a1.x += h3.x; a1.y += h3.y; a1.z += h3.z; a1.w += h3.w; }

    for (int j = 16; j < cnt; j += 8) {
        int t0 = clampidx(sr[j + q]);
        int t1 = clampidx(sr[j + 4 + q]);
        float4 g0 = *(const float4*)&g_h[t0 * DOUT + c4 * 4];
        float4 g1 = *(const float4*)&g_h[t1 * DOUT + c4 * 4];
        if (j + q     < cnt) { a0.x += g0.x; a0.y += g0.y; a0.z += g0.z; a0.w += g0.w; }
        if (j + 4 + q < cnt) { a1.x += g1.x; a1.y += g1.y; a1.z += g1.z; a1.w += g1.w; }
    }

    a0.x += a1.x; a0.y += a1.y; a0.z += a1.z; a0.w += a1.w;

    a0.x += __shfl_xor_sync(0xffffffffu, a0.x, 8);
    a0.y += __shfl_xor_sync(0xffffffffu, a0.y, 8);
    a0.z += __shfl_xor_sync(0xffffffffu, a0.z, 8);
    a0.w += __shfl_xor_sync(0xffffffffu, a0.w, 8);
    a0.x += __shfl_xor_sync(0xffffffffu, a0.x, 16);
    a0.y += __shfl_xor_sync(0xffffffffu, a0.y, 16);
    a0.z += __shfl_xor_sync(0xffffffffu, a0.z, 16);
    a0.w += __shfl_xor_sync(0xffffffffu, a0.w, 16);

    if (lane < 8) {
        if (cnt_raw <= CAP) {
            oval.x = fmaf(a0.x, dd, oval.x);
            oval.y = fmaf(a0.y, dd, oval.y);
            oval.z = fmaf(a0.z, dd, oval.z);
            oval.w = fmaf(a0.w, dd, oval.w);
            *op = oval;
        } else {
            float* os = (float*)op;
            atomicAdd(os + 0, a0.x * dd);
            atomicAdd(os + 1, a0.y * dd);
            atomicAdd(os + 2, a0.z * dd);
            atomicAdd(os + 3, a0.w * dd);
        }
    }
}

// ---------------------------------------------------------------------------
// Launch graph (R11-proven):
//   s0: memset(fill) -> k_place ─┐
//   s2: k_gemm (independent)    ─┴─ join -> k_scale -> k_agg
// Stream/events created lazily on the FIRST (uncaptured) call only.
// ---------------------------------------------------------------------------
extern "C" void kernel_launch(void* const* d_in, const int* in_sizes, int n_in,
                              void* d_out, int out_size) {
    const float* x  = (const float*)d_in[0];
    const void*  ei = d_in[1];
    const float* W  = (const float*)d_in[2];
    const float* b  = (const float*)d_in[3];
    float* out = (float*)d_out;

    int n = in_sizes[0] / DIN;   // 100000
    int E = in_sizes[1] / 2;     // 1600000

    static cudaStream_t s2 = nullptr;
    static cudaEvent_t evFork = nullptr, evJoin = nullptr;
    if (!s2) {
        cudaStreamCreateWithFlags(&s2, cudaStreamNonBlocking);
        cudaEventCreateWithFlags(&evFork, cudaEventDisableTiming);
        cudaEventCreateWithFlags(&evJoin, cudaEventDisableTiming);
    }

    void* fill_ptr = nullptr;
    cudaGetSymbolAddress(&fill_ptr, g_fill);

    // fork: gemm branch on s2 (touches only x, W, g_h)
    cudaEventRecord(evFork, 0);
    cudaStreamWaitEvent(s2, evFork, 0);
    k_gemm<<<(n + BM - 1) / BM, 256, 0, s2>>>(x, W, n);
    cudaEventRecord(evJoin, s2);

    // place branch on stream 0
    cudaMemsetAsync(fill_ptr, 0, (NMAX + 1) * sizeof(int), 0);
    k_place<<<(E + 255) / 256, 256>>>(ei, E);

    // join, then epilogue + aggregation
    cudaStreamWaitEvent(0, evJoin, 0);
    k_scale<<<(n * 8 + 255) / 256, 256>>>(b, out, n);

    int nb_agg = (n + 3) / 4;
    k_agg<<<nb_agg + 16, 128>>>(out, n, nb_agg);
}